// round 3
// baseline (speedup 1.0000x reference)
#include <cuda_runtime.h>
#include <cuda_bf16.h>
#include <cstdint>

// MHC layer: B=8192, N=4, C=4096, f32. HBM-bound fusion.
// R3: 3 CTAs/SM. Params (sigmoid gates + Sinkhorn P) computed by thread 0
// into smem; agg recomputed in pass B -> regs <= 42 so 3 CTAs fit the RF.

#define C_DIM 4096
#define NS 4
#define THREADS 512
#define VEC 2               // float4 chunks per thread per stream: 4096/4/512
#define EPS 1e-6f
#define SMEM_BYTES (NS * C_DIM * 4)   // 64 KB: x row as float4[4][1024]

__device__ __forceinline__ uint32_t smem_u32(const void* p) {
    uint32_t a;
    asm("{ .reg .u64 t; cvta.to.shared.u64 t, %1; cvt.u32.u64 %0, t; }"
        : "=r"(a) : "l"(p));
    return a;
}

__global__ __launch_bounds__(THREADS, 3)
void mhc_kernel(const float* __restrict__ x,
                const float* __restrict__ w,
                const float* __restrict__ H_pre,
                const float* __restrict__ H_post,
                const float* __restrict__ H_res,
                float* __restrict__ out)
{
    extern __shared__ float4 sx[];          // [NS * C_DIM/4] = [4096] float4
    __shared__ float red[THREADS / 32];
    __shared__ float sp[24];                // [0:4)=hpre [4:8)=hpost [8:24)=P

    const int b = blockIdx.x;
    const int t = threadIdx.x;

    // ---- kick off async copy of x[b,:,:] into smem (bypasses RF) ----
    const float4* __restrict__ xr =
        reinterpret_cast<const float4*>(x + (size_t)b * NS * C_DIM);
    {
        const uint32_t sbase = smem_u32(sx);
#pragma unroll
        for (int n = 0; n < NS; n++)
#pragma unroll
            for (int k = 0; k < VEC; k++) {
                const int idx = n * (C_DIM / 4) + t + k * THREADS;
                asm volatile("cp.async.cg.shared.global [%0], [%1], 16;"
                             :: "r"(sbase + idx * 16), "l"(xr + idx));
            }
        asm volatile("cp.async.commit_group;");
    }

    // ---- thread 0: tiny parameter math into smem while copies fly ----
    if (t == 0) {
#pragma unroll
        for (int n = 0; n < NS; n++) {
            sp[n]      = 1.0f / (1.0f + expf(-H_pre[n]));
            sp[4 + n]  = 2.0f / (1.0f + expf(-H_post[n]));
        }
        float P[NS][NS];
#pragma unroll
        for (int i = 0; i < NS; i++)
#pragma unroll
            for (int j = 0; j < NS; j++)
                P[i][j] = expf(H_res[i * NS + j]);
#pragma unroll
        for (int it = 0; it < 3; it++) {
#pragma unroll
            for (int i = 0; i < NS; i++) {
                float inv = 1.0f / (P[i][0] + P[i][1] + P[i][2] + P[i][3] + EPS);
#pragma unroll
                for (int j = 0; j < NS; j++) P[i][j] *= inv;
            }
#pragma unroll
            for (int j = 0; j < NS; j++) {
                float inv = 1.0f / (P[0][j] + P[1][j] + P[2][j] + P[3][j] + EPS);
#pragma unroll
                for (int i = 0; i < NS; i++) P[i][j] *= inv;
            }
        }
#pragma unroll
        for (int i = 0; i < NS; i++)
#pragma unroll
            for (int j = 0; j < NS; j++)
                sp[8 + i * NS + j] = P[i][j];
    }

    asm volatile("cp.async.wait_group 0;" ::: "memory");
    __syncthreads();

    const float hp0 = sp[0], hp1 = sp[1], hp2 = sp[2], hp3 = sp[3];

    // ---- pass A: gated aggregation + bf16 round-trip -> sum of squares ----
    float ss = 0.0f;
#pragma unroll
    for (int k = 0; k < VEC; k++) {
        const int c4 = t + k * THREADS;
        const float4 v0 = sx[0 * (C_DIM / 4) + c4];
        const float4 v1 = sx[1 * (C_DIM / 4) + c4];
        const float4 v2 = sx[2 * (C_DIM / 4) + c4];
        const float4 v3 = sx[3 * (C_DIM / 4) + c4];
        float ax = hp0*v0.x + hp1*v1.x + hp2*v2.x + hp3*v3.x;
        float ay = hp0*v0.y + hp1*v1.y + hp2*v2.y + hp3*v3.y;
        float az = hp0*v0.z + hp1*v1.z + hp2*v2.z + hp3*v3.z;
        float aw = hp0*v0.w + hp1*v1.w + hp2*v2.w + hp3*v3.w;
        ax = __bfloat162float(__float2bfloat16(ax));
        ay = __bfloat162float(__float2bfloat16(ay));
        az = __bfloat162float(__float2bfloat16(az));
        aw = __bfloat162float(__float2bfloat16(aw));
        ss += ax*ax + ay*ay + az*az + aw*aw;
    }

    // ---- block reduce sum of squares ----
#pragma unroll
    for (int off = 16; off > 0; off >>= 1)
        ss += __shfl_xor_sync(0xFFFFFFFFu, ss, off);
    if ((t & 31) == 0) red[t >> 5] = ss;
    __syncthreads();
    if (t < 32) {
        float s = (t < THREADS / 32) ? red[t] : 0.0f;
#pragma unroll
        for (int off = 8; off > 0; off >>= 1)
            s += __shfl_xor_sync(0xFFFFFFFFu, s, off);
        if (t == 0) red[0] = s;
    }
    __syncthreads();
    const float inv_rms = rsqrtf(red[0] * (1.0f / C_DIM) + EPS);

    // ---- pass B: recompute agg -> y_norm; 4x4 mix + gated add; write ----
    const float4* __restrict__ wr = reinterpret_cast<const float4*>(w);
    float4* __restrict__ outr =
        reinterpret_cast<float4*>(out + (size_t)b * NS * C_DIM);
#pragma unroll
    for (int k = 0; k < VEC; k++) {
        const int c4 = t + k * THREADS;
        const float4 v0 = sx[0 * (C_DIM / 4) + c4];
        const float4 v1 = sx[1 * (C_DIM / 4) + c4];
        const float4 v2 = sx[2 * (C_DIM / 4) + c4];
        const float4 v3 = sx[3 * (C_DIM / 4) + c4];

        float ax = hp0*v0.x + hp1*v1.x + hp2*v2.x + hp3*v3.x;
        float ay = hp0*v0.y + hp1*v1.y + hp2*v2.y + hp3*v3.y;
        float az = hp0*v0.z + hp1*v1.z + hp2*v2.z + hp3*v3.z;
        float aw = hp0*v0.w + hp1*v1.w + hp2*v2.w + hp3*v3.w;
        ax = __bfloat162float(__float2bfloat16(ax));
        ay = __bfloat162float(__float2bfloat16(ay));
        az = __bfloat162float(__float2bfloat16(az));
        aw = __bfloat162float(__float2bfloat16(aw));

        const float4 w4 = wr[c4];
        const float yx = ax * inv_rms * w4.x;
        const float yy = ay * inv_rms * w4.y;
        const float yz = az * inv_rms * w4.z;
        const float yw = aw * inv_rms * w4.w;

#pragma unroll
        for (int i = 0; i < NS; i++) {
            const float p0 = sp[8 + i * NS + 0];
            const float p1 = sp[8 + i * NS + 1];
            const float p2 = sp[8 + i * NS + 2];
            const float p3 = sp[8 + i * NS + 3];
            const float hq = sp[4 + i];
            float4 o;
            o.x = p0*v0.x + p1*v1.x + p2*v2.x + p3*v3.x + hq*yx;
            o.y = p0*v0.y + p1*v1.y + p2*v2.y + p3*v3.y + hq*yy;
            o.z = p0*v0.z + p1*v1.z + p2*v2.z + p3*v3.z + hq*yz;
            o.w = p0*v0.w + p1*v1.w + p2*v2.w + p3*v3.w + hq*yw;
            outr[i * (C_DIM / 4) + c4] = o;
        }
    }
}

extern "C" void kernel_launch(void* const* d_in, const int* in_sizes, int n_in,
                              void* d_out, int out_size)
{
    const float* x      = (const float*)d_in[0];  // [8192, 4, 4096]
    const float* w      = (const float*)d_in[1];  // [4096]
    const float* H_pre  = (const float*)d_in[2];  // [4]
    const float* H_post = (const float*)d_in[3];  // [4]
    const float* H_res  = (const float*)d_in[4];  // [4, 4]
    float* out = (float*)d_out;                   // [8192, 4, 4096]

    cudaFuncSetAttribute(mhc_kernel,
                         cudaFuncAttributeMaxDynamicSharedMemorySize, SMEM_BYTES);

    const int B = in_sizes[0] / (NS * C_DIM);     // 8192
    mhc_kernel<<<B, THREADS, SMEM_BYTES>>>(x, w, H_pre, H_post, H_res, out);
}

// round 4
// speedup vs baseline: 1.5930x; 1.5930x over previous
#include <cuda_runtime.h>
#include <cuda_bf16.h>
#include <cstdint>

// MHC layer: B=8192, N=4, C=4096, f32. HBM-bound fusion.
// R4: 1 CTA/SM x 1024 threads, double-buffered smem (2x64KB), 8 rows/CTA.
// Prefetch row b+1 (cp.async) overlaps compute+store of row b ->
// continuous DRAM read+write streams within one CTA.

#define C_DIM 4096
#define NS 4
#define THREADS 1024            // = C_DIM/4 -> one float4 per stream per thread
#define ROWS_PER_CTA 8
#define EPS 1e-6f
#define ROW_F4 (NS * C_DIM / 4)             // 4096 float4 per row buffer
#define SMEM_BYTES (2 * ROW_F4 * 16)        // 128 KB: two row buffers

__device__ __forceinline__ uint32_t smem_u32(const void* p) {
    uint32_t a;
    asm("{ .reg .u64 t; cvta.to.shared.u64 t, %1; cvt.u32.u64 %0, t; }"
        : "=r"(a) : "l"(p));
    return a;
}

__global__ __launch_bounds__(THREADS, 1)
void mhc_kernel(const float* __restrict__ x,
                const float* __restrict__ w,
                const float* __restrict__ H_pre,
                const float* __restrict__ H_post,
                const float* __restrict__ H_res,
                float* __restrict__ out)
{
    extern __shared__ float4 sx[];          // [2][ROW_F4]
    __shared__ float red[THREADS / 32];
    __shared__ float sp[24];                // [0:4)=hpre [4:8)=hpost [8:24)=P

    const int t = threadIdx.x;
    const int b0 = blockIdx.x * ROWS_PER_CTA;
    const uint32_t sbase = smem_u32(sx);

    // ---- prologue: prefetch first row into buffer 0 ----
    {
        const float4* __restrict__ xr =
            reinterpret_cast<const float4*>(x + (size_t)b0 * NS * C_DIM);
#pragma unroll
        for (int n = 0; n < NS; n++) {
            const int idx = n * THREADS + t;
            asm volatile("cp.async.cg.shared.global [%0], [%1], 16;"
                         :: "r"(sbase + idx * 16), "l"(xr + idx));
        }
        asm volatile("cp.async.commit_group;");
    }

    // ---- thread 0: tiny parameter math into smem while copies fly ----
    if (t == 0) {
#pragma unroll
        for (int n = 0; n < NS; n++) {
            sp[n]     = 1.0f / (1.0f + expf(-H_pre[n]));
            sp[4 + n] = 2.0f / (1.0f + expf(-H_post[n]));
        }
        float P[NS][NS];
#pragma unroll
        for (int i = 0; i < NS; i++)
#pragma unroll
            for (int j = 0; j < NS; j++)
                P[i][j] = expf(H_res[i * NS + j]);
#pragma unroll
        for (int it = 0; it < 3; it++) {
#pragma unroll
            for (int i = 0; i < NS; i++) {
                float inv = 1.0f / (P[i][0] + P[i][1] + P[i][2] + P[i][3] + EPS);
#pragma unroll
                for (int j = 0; j < NS; j++) P[i][j] *= inv;
            }
#pragma unroll
            for (int j = 0; j < NS; j++) {
                float inv = 1.0f / (P[0][j] + P[1][j] + P[2][j] + P[3][j] + EPS);
#pragma unroll
                for (int i = 0; i < NS; i++) P[i][j] *= inv;
            }
        }
#pragma unroll
        for (int i = 0; i < NS; i++)
#pragma unroll
            for (int j = 0; j < NS; j++)
                sp[8 + i * NS + j] = P[i][j];
    }
    __syncthreads();

    // ---- params into registers (kept across the row loop) ----
    const float hp0 = sp[0], hp1 = sp[1], hp2 = sp[2], hp3 = sp[3];
    float Pr[NS][NS], hq[NS];
#pragma unroll
    for (int i = 0; i < NS; i++) {
        hq[i] = sp[4 + i];
#pragma unroll
        for (int j = 0; j < NS; j++) Pr[i][j] = sp[8 + i * NS + j];
    }

    const float4* __restrict__ wr = reinterpret_cast<const float4*>(w);

    int parity = 0;
#pragma unroll 1
    for (int r = 0; r < ROWS_PER_CTA; r++) {
        const int b = b0 + r;
        const bool has_next = (r + 1 < ROWS_PER_CTA);

        // ---- prefetch next row into the other buffer ----
        if (has_next) {
            const float4* __restrict__ xr =
                reinterpret_cast<const float4*>(x + (size_t)(b + 1) * NS * C_DIM);
            const uint32_t sb = sbase + (1 - parity) * (ROW_F4 * 16);
#pragma unroll
            for (int n = 0; n < NS; n++) {
                const int idx = n * THREADS + t;
                asm volatile("cp.async.cg.shared.global [%0], [%1], 16;"
                             :: "r"(sb + idx * 16), "l"(xr + idx));
            }
            asm volatile("cp.async.commit_group;");
            asm volatile("cp.async.wait_group 1;" ::: "memory");
        } else {
            asm volatile("cp.async.wait_group 0;" ::: "memory");
        }
        __syncthreads();

        const float4* __restrict__ sb = sx + parity * ROW_F4;

        // ---- pass A: gated agg + bf16 round-trip -> sum of squares ----
        const float4 v0 = sb[0 * THREADS + t];
        const float4 v1 = sb[1 * THREADS + t];
        const float4 v2 = sb[2 * THREADS + t];
        const float4 v3 = sb[3 * THREADS + t];
        float ax = hp0*v0.x + hp1*v1.x + hp2*v2.x + hp3*v3.x;
        float ay = hp0*v0.y + hp1*v1.y + hp2*v2.y + hp3*v3.y;
        float az = hp0*v0.z + hp1*v1.z + hp2*v2.z + hp3*v3.z;
        float aw = hp0*v0.w + hp1*v1.w + hp2*v2.w + hp3*v3.w;
        ax = __bfloat162float(__float2bfloat16(ax));
        ay = __bfloat162float(__float2bfloat16(ay));
        az = __bfloat162float(__float2bfloat16(az));
        aw = __bfloat162float(__float2bfloat16(aw));
        float ss = ax*ax + ay*ay + az*az + aw*aw;

        // ---- block reduce (32 warps) ----
#pragma unroll
        for (int off = 16; off > 0; off >>= 1)
            ss += __shfl_xor_sync(0xFFFFFFFFu, ss, off);
        if ((t & 31) == 0) red[t >> 5] = ss;
        __syncthreads();
        if (t < 32) {
            float s = red[t];
#pragma unroll
            for (int off = 16; off > 0; off >>= 1)
                s += __shfl_xor_sync(0xFFFFFFFFu, s, off);
            if (t == 0) red[0] = s;
        }
        __syncthreads();
        const float inv_rms = rsqrtf(red[0] * (1.0f / C_DIM) + EPS);

        // ---- pass B: y_norm, 4x4 mix + gated add, float4 stores ----
        const float4 w4 = wr[t];
        const float yx = ax * inv_rms * w4.x;
        const float yy = ay * inv_rms * w4.y;
        const float yz = az * inv_rms * w4.z;
        const float yw = aw * inv_rms * w4.w;

        float4* __restrict__ outr =
            reinterpret_cast<float4*>(out + (size_t)b * NS * C_DIM);
#pragma unroll
        for (int i = 0; i < NS; i++) {
            float4 o;
            o.x = Pr[i][0]*v0.x + Pr[i][1]*v1.x + Pr[i][2]*v2.x + Pr[i][3]*v3.x + hq[i]*yx;
            o.y = Pr[i][0]*v0.y + Pr[i][1]*v1.y + Pr[i][2]*v2.y + Pr[i][3]*v3.y + hq[i]*yy;
            o.z = Pr[i][0]*v0.z + Pr[i][1]*v1.z + Pr[i][2]*v2.z + Pr[i][3]*v3.z + hq[i]*yz;
            o.w = Pr[i][0]*v0.w + Pr[i][1]*v1.w + Pr[i][2]*v2.w + Pr[i][3]*v3.w + hq[i]*yw;
            outr[i * THREADS + t] = o;
        }

        // buffer read complete before next iter prefetches into it
        __syncthreads();
        parity ^= 1;
    }
}

extern "C" void kernel_launch(void* const* d_in, const int* in_sizes, int n_in,
                              void* d_out, int out_size)
{
    const float* x      = (const float*)d_in[0];  // [8192, 4, 4096]
    const float* w      = (const float*)d_in[1];  // [4096]
    const float* H_pre  = (const float*)d_in[2];  // [4]
    const float* H_post = (const float*)d_in[3];  // [4]
    const float* H_res  = (const float*)d_in[4];  // [4, 4]
    float* out = (float*)d_out;                   // [8192, 4, 4096]

    cudaFuncSetAttribute(mhc_kernel,
                         cudaFuncAttributeMaxDynamicSharedMemorySize, SMEM_BYTES);

    const int B = in_sizes[0] / (NS * C_DIM);     // 8192
    mhc_kernel<<<B / ROWS_PER_CTA, THREADS, SMEM_BYTES>>>(x, w, H_pre, H_post, H_res, out);
}